// round 1
// baseline (speedup 1.0000x reference)
#include <cuda_runtime.h>

#define NNODES 8192
#define NF 1024
#define NH 512
#define NZ 32

// ---- scratch (device globals; no allocation allowed) ----
__device__ float g_xw0[NNODES * NH];   // x @ W0
__device__ float g_h[NNODES * NH];     // relu(spmm + b0)
__device__ float g_hw[NNODES * 64];    // h @ [W1 | W2]
__device__ float g_z[NNODES * 64];     // [mu | logvar]
__device__ int   g_rowptr[NNODES + 1];

// ---------------------------------------------------------------------------
// Build CSR row pointers from sorted adj_rows via per-row lower_bound.
// ---------------------------------------------------------------------------
__global__ void k_rowptr(const int* __restrict__ rows, int E) {
    int r = blockIdx.x * blockDim.x + threadIdx.x;
    if (r > NNODES) return;
    int lo = 0, hi = E;
    while (lo < hi) {
        int mid = (lo + hi) >> 1;
        if (rows[mid] < r) lo = mid + 1; else hi = mid;
    }
    g_rowptr[r] = lo;
}

// ---------------------------------------------------------------------------
// GEMM1: g_xw0 = x[8192,1024] @ W0[1024,512]. 128x128 tile, BK=16, 8x8/thread.
// ---------------------------------------------------------------------------
__global__ __launch_bounds__(256) void k_gemm1(const float* __restrict__ A,
                                               const float* __restrict__ B) {
    __shared__ float As[16][128 + 4];
    __shared__ float Bs[16][128];
    int tid = threadIdx.x;
    int bm = blockIdx.y * 128, bn = blockIdx.x * 128;
    int tx = tid & 15, ty = tid >> 4;

    float acc[8][8];
#pragma unroll
    for (int i = 0; i < 8; i++)
#pragma unroll
        for (int j = 0; j < 8; j++) acc[i][j] = 0.f;

    for (int k0 = 0; k0 < NF; k0 += 16) {
        // Load A tile 128x16 (transposed into As[k][m])
#pragma unroll
        for (int l = 0; l < 2; l++) {
            int idx = tid * 2 + l;              // 512 float4s
            int row = idx >> 2, c4 = (idx & 3) * 4;
            float4 v = *(const float4*)&A[(size_t)(bm + row) * NF + k0 + c4];
            As[c4 + 0][row] = v.x; As[c4 + 1][row] = v.y;
            As[c4 + 2][row] = v.z; As[c4 + 3][row] = v.w;
        }
        // Load B tile 16x128
#pragma unroll
        for (int l = 0; l < 2; l++) {
            int idx = tid * 2 + l;
            int row = idx >> 5, c4 = (idx & 31) * 4;
            *(float4*)&Bs[row][c4] = *(const float4*)&B[(size_t)(k0 + row) * NH + bn + c4];
        }
        __syncthreads();
#pragma unroll
        for (int k = 0; k < 16; k++) {
            float a[8], b[8];
            *(float4*)a       = *(const float4*)&As[k][ty * 8];
            *(float4*)(a + 4) = *(const float4*)&As[k][ty * 8 + 4];
            *(float4*)b       = *(const float4*)&Bs[k][tx * 8];
            *(float4*)(b + 4) = *(const float4*)&Bs[k][tx * 8 + 4];
#pragma unroll
            for (int i = 0; i < 8; i++)
#pragma unroll
                for (int j = 0; j < 8; j++) acc[i][j] += a[i] * b[j];
        }
        __syncthreads();
    }
#pragma unroll
    for (int i = 0; i < 8; i++) {
        size_t off = (size_t)(bm + ty * 8 + i) * NH + bn + tx * 8;
        float4 o0 = make_float4(acc[i][0], acc[i][1], acc[i][2], acc[i][3]);
        float4 o1 = make_float4(acc[i][4], acc[i][5], acc[i][6], acc[i][7]);
        *(float4*)&g_xw0[off]     = o0;
        *(float4*)&g_xw0[off + 4] = o1;
    }
}

// ---------------------------------------------------------------------------
// SpMM1: g_h[r,:] = relu(sum_e vals[e]*g_xw0[cols[e],:] + b0). 1 block/row,
// 256 threads x 2 features, 4-way edge unroll for MLP.
// ---------------------------------------------------------------------------
__global__ __launch_bounds__(256) void k_spmm1(const float* __restrict__ vals,
                                               const int* __restrict__ cols,
                                               const float* __restrict__ bias) {
    int r = blockIdx.x;
    int t = threadIdx.x;
    int s = g_rowptr[r], e = g_rowptr[r + 1];
    float a0 = 0, a1 = 0, a2 = 0, a3 = 0;
    float c0 = 0, c1 = 0, c2 = 0, c3 = 0;
    int i = s;
    for (; i + 4 <= e; i += 4) {
        float v0 = vals[i], v1 = vals[i + 1], v2 = vals[i + 2], v3 = vals[i + 3];
        int   j0 = cols[i], j1 = cols[i + 1], j2 = cols[i + 2], j3 = cols[i + 3];
        a0 += v0 * g_xw0[(size_t)j0 * NH + t];
        c0 += v0 * g_xw0[(size_t)j0 * NH + t + 256];
        a1 += v1 * g_xw0[(size_t)j1 * NH + t];
        c1 += v1 * g_xw0[(size_t)j1 * NH + t + 256];
        a2 += v2 * g_xw0[(size_t)j2 * NH + t];
        c2 += v2 * g_xw0[(size_t)j2 * NH + t + 256];
        a3 += v3 * g_xw0[(size_t)j3 * NH + t];
        c3 += v3 * g_xw0[(size_t)j3 * NH + t + 256];
    }
    for (; i < e; i++) {
        float v = vals[i]; int j = cols[i];
        a0 += v * g_xw0[(size_t)j * NH + t];
        c0 += v * g_xw0[(size_t)j * NH + t + 256];
    }
    float h0 = (a0 + a1) + (a2 + a3) + bias[t];
    float h1 = (c0 + c1) + (c2 + c3) + bias[t + 256];
    g_h[(size_t)r * NH + t]       = fmaxf(h0, 0.f);
    g_h[(size_t)r * NH + t + 256] = fmaxf(h1, 0.f);
}

// ---------------------------------------------------------------------------
// GEMM2: g_hw[r, 0:32] = h[r] @ W1 ; g_hw[r, 32:64] = h[r] @ W2.
// blockDim (64,4): 4 rows per block; warp = one 32-col half -> coalesced W.
// ---------------------------------------------------------------------------
__global__ __launch_bounds__(256) void k_gemm2(const float* __restrict__ W1,
                                               const float* __restrict__ W2) {
    int tx = threadIdx.x;                        // 0..63
    int r = blockIdx.x * 4 + threadIdx.y;
    const float* W = (tx < 32) ? W1 : W2;
    int j = tx & 31;
    const float* hrow = g_h + (size_t)r * NH;
    float a0 = 0, a1 = 0, a2 = 0, a3 = 0;
#pragma unroll 4
    for (int k = 0; k < NH; k += 4) {
        a0 += hrow[k + 0] * W[(k + 0) * NZ + j];
        a1 += hrow[k + 1] * W[(k + 1) * NZ + j];
        a2 += hrow[k + 2] * W[(k + 2) * NZ + j];
        a3 += hrow[k + 3] * W[(k + 3) * NZ + j];
    }
    g_hw[(size_t)r * 64 + tx] = (a0 + a1) + (a2 + a3);
}

// ---------------------------------------------------------------------------
// SpMM2: mu/logvar = relu(spmm(hw) + bias). Also scatters z/mu/logvar into
// the output buffer and g_z (decoder input).
// ---------------------------------------------------------------------------
__global__ __launch_bounds__(256) void k_spmm2(const float* __restrict__ vals,
                                               const int* __restrict__ cols,
                                               const float* __restrict__ b1,
                                               const float* __restrict__ b2,
                                               float* __restrict__ out) {
    int tx = threadIdx.x;                        // 0..63
    int r = blockIdx.x * 4 + threadIdx.y;
    int s = g_rowptr[r], e = g_rowptr[r + 1];
    float a0 = 0, a1 = 0, a2 = 0, a3 = 0;
    int i = s;
    for (; i + 4 <= e; i += 4) {
        float v0 = vals[i], v1 = vals[i + 1], v2 = vals[i + 2], v3 = vals[i + 3];
        int   j0 = cols[i], j1 = cols[i + 1], j2 = cols[i + 2], j3 = cols[i + 3];
        a0 += v0 * g_hw[(size_t)j0 * 64 + tx];
        a1 += v1 * g_hw[(size_t)j1 * 64 + tx];
        a2 += v2 * g_hw[(size_t)j2 * 64 + tx];
        a3 += v3 * g_hw[(size_t)j3 * 64 + tx];
    }
    for (; i < e; i++) {
        a0 += vals[i] * g_hw[(size_t)cols[i] * 64 + tx];
    }
    float bias = (tx < 32) ? b1[tx] : b2[tx - 32];
    float v = fmaxf((a0 + a1) + (a2 + a3) + bias, 0.f);
    g_z[(size_t)r * 64 + tx] = v;

    size_t base = (size_t)NNODES * NNODES;       // after adj_recon
    if (tx < 32) {
        out[base + (size_t)r * NZ + tx] = v;                       // z
        out[base + (size_t)NNODES * NZ + (size_t)r * NZ + tx] = v; // mu
    } else {
        out[base + (size_t)NNODES * NZ * 2 + (size_t)r * NZ + (tx - 32)] = v; // logvar
    }
}

// ---------------------------------------------------------------------------
// Decoder: adj_recon = sigmoid(z @ z^T). 128x128 tile, K=32, 8x8/thread.
// ---------------------------------------------------------------------------
__global__ __launch_bounds__(256) void k_decoder(float* __restrict__ out) {
    __shared__ float sA[NZ][132];
    __shared__ float sB[NZ][132];
    int tid = threadIdx.x;
    int i0 = blockIdx.y * 128, j0 = blockIdx.x * 128;

#pragma unroll
    for (int l = 0; l < 4; l++) {
        int idx = l * 256 + tid;                 // 1024 float4s per tile
        int row = idx >> 3, q = idx & 7;         // q*4 = feature offset (0..28)
        float4 va = *(const float4*)&g_z[(size_t)(i0 + row) * 64 + q * 4];
        sA[q * 4 + 0][row] = va.x; sA[q * 4 + 1][row] = va.y;
        sA[q * 4 + 2][row] = va.z; sA[q * 4 + 3][row] = va.w;
        float4 vb = *(const float4*)&g_z[(size_t)(j0 + row) * 64 + q * 4];
        sB[q * 4 + 0][row] = vb.x; sB[q * 4 + 1][row] = vb.y;
        sB[q * 4 + 2][row] = vb.z; sB[q * 4 + 3][row] = vb.w;
    }
    __syncthreads();

    int tx = tid & 15, ty = tid >> 4;
    float acc[8][8];
#pragma unroll
    for (int i = 0; i < 8; i++)
#pragma unroll
        for (int j = 0; j < 8; j++) acc[i][j] = 0.f;

#pragma unroll
    for (int k = 0; k < NZ; k++) {
        float a[8], b[8];
        *(float4*)a       = *(const float4*)&sA[k][ty * 8];
        *(float4*)(a + 4) = *(const float4*)&sA[k][ty * 8 + 4];
        *(float4*)b       = *(const float4*)&sB[k][tx * 8];
        *(float4*)(b + 4) = *(const float4*)&sB[k][tx * 8 + 4];
#pragma unroll
        for (int i = 0; i < 8; i++)
#pragma unroll
            for (int j = 0; j < 8; j++) acc[i][j] += a[i] * b[j];
    }

#pragma unroll
    for (int i = 0; i < 8; i++) {
        float o[8];
#pragma unroll
        for (int j = 0; j < 8; j++) o[j] = 1.f / (1.f + __expf(-acc[i][j]));
        size_t off = (size_t)(i0 + ty * 8 + i) * NNODES + j0 + tx * 8;
        *(float4*)&out[off]     = make_float4(o[0], o[1], o[2], o[3]);
        *(float4*)&out[off + 4] = make_float4(o[4], o[5], o[6], o[7]);
    }
}

// ---------------------------------------------------------------------------
extern "C" void kernel_launch(void* const* d_in, const int* in_sizes, int n_in,
                              void* d_out, int out_size) {
    const float* x    = (const float*)d_in[0];
    const float* vals = (const float*)d_in[1];
    const float* W0   = (const float*)d_in[2];
    const float* b0   = (const float*)d_in[3];
    const float* W1   = (const float*)d_in[4];
    const float* b1   = (const float*)d_in[5];
    const float* W2   = (const float*)d_in[6];
    const float* b2   = (const float*)d_in[7];
    const int*   rows = (const int*)d_in[8];
    const int*   cols = (const int*)d_in[9];
    int E = in_sizes[1];
    float* out = (float*)d_out;

    k_rowptr<<<(NNODES + 256) / 256, 256>>>(rows, E);
    k_gemm1<<<dim3(NH / 128, NNODES / 128), 256>>>(x, W0);
    k_spmm1<<<NNODES, 256>>>(vals, cols, b0);
    k_gemm2<<<NNODES / 4, dim3(64, 4)>>>(W1, W2);
    k_spmm2<<<NNODES / 4, dim3(64, 4)>>>(vals, cols, b1, b2, out);
    k_decoder<<<dim3(NNODES / 128, NNODES / 128), 256>>>(out);
}

// round 3
// speedup vs baseline: 1.6653x; 1.6653x over previous
#include <cuda_runtime.h>

#define NNODES 8192
#define NF 1024
#define NH 512
#define NZ 32

// ---- scratch (device globals; no allocation allowed) ----
__device__ float    g_xw0[NNODES * NH];     // x @ W0 (fp32)
__device__ unsigned g_h[NNODES * NH];       // relu(spmm + b0), tf32 bits
__device__ unsigned g_wcat[NH * 64];        // [W1 | W2], tf32 bits
__device__ float    g_hw[NNODES * 64];      // h @ [W1|W2] (fp32)
__device__ unsigned g_z[NNODES * 64];       // [mu | logvar], tf32 bits
__device__ int      g_rowptr[NNODES + 1];

__device__ __forceinline__ unsigned f2tf(float f) {
    unsigned u;
    asm("cvt.rna.tf32.f32 %0, %1;" : "=r"(u) : "f"(f));
    return u;
}

__device__ __forceinline__ void mma_tf32(float c[4], const unsigned a[4],
                                         const unsigned b[2]) {
    asm volatile(
        "mma.sync.aligned.m16n8k8.row.col.f32.tf32.tf32.f32 "
        "{%0,%1,%2,%3}, {%4,%5,%6,%7}, {%8,%9}, {%0,%1,%2,%3};"
        : "+f"(c[0]), "+f"(c[1]), "+f"(c[2]), "+f"(c[3])
        : "r"(a[0]), "r"(a[1]), "r"(a[2]), "r"(a[3]), "r"(b[0]), "r"(b[1]));
}

// ---------------------------------------------------------------------------
// CSR row pointers (binary search on sorted rows).
// ---------------------------------------------------------------------------
__global__ void k_rowptr(const int* __restrict__ rows, int E) {
    int r = blockIdx.x * blockDim.x + threadIdx.x;
    if (r > NNODES) return;
    int lo = 0, hi = E;
    while (lo < hi) {
        int mid = (lo + hi) >> 1;
        if (rows[mid] < r) lo = mid + 1; else hi = mid;
    }
    g_rowptr[r] = lo;
}

// ---------------------------------------------------------------------------
// Pack [W1 | W2] -> g_wcat as tf32 bits. W1/W2 are [512][32].
// ---------------------------------------------------------------------------
__global__ void k_pack_w(const float* __restrict__ W1,
                         const float* __restrict__ W2) {
    int idx = blockIdx.x * blockDim.x + threadIdx.x;
    if (idx >= NH * 64) return;
    int row = idx >> 6, c = idx & 63;
    float v = (c < 32) ? W1[row * NZ + c] : W2[row * NZ + (c - 32)];
    g_wcat[idx] = f2tf(v);
}

// ---------------------------------------------------------------------------
// GEMM1 (tf32 mma): g_xw0 = x[8192,1024] @ W0[1024,512].
// 128x128 tile, BK=16, 8 warps (4 in M x 2 in N), warp tile 32x64.
// ---------------------------------------------------------------------------
__global__ __launch_bounds__(256) void k_gemm1(const float* __restrict__ A,
                                               const float* __restrict__ B) {
    __shared__ unsigned As[16][132];   // [k][m]
    __shared__ unsigned Bs[16][132];   // [k][n]
    int tid = threadIdx.x, lane = tid & 31, wid = tid >> 5;
    int g = lane >> 2, t = lane & 3;
    int bm = blockIdx.y * 128, bn = blockIdx.x * 128;
    int wm = (wid & 3) * 32, wn = (wid >> 2) * 64;

    float acc[2][8][4];
#pragma unroll
    for (int mi = 0; mi < 2; mi++)
#pragma unroll
        for (int ni = 0; ni < 8; ni++)
#pragma unroll
            for (int j = 0; j < 4; j++) acc[mi][ni][j] = 0.f;

    for (int k0 = 0; k0 < NF; k0 += 16) {
#pragma unroll
        for (int l = 0; l < 2; l++) {
            int idx = tid * 2 + l;                    // 512 float4 loads each
            int arow = idx >> 2, ac4 = (idx & 3) * 4;
            float4 v = *(const float4*)&A[(size_t)(bm + arow) * NF + k0 + ac4];
            As[ac4 + 0][arow] = f2tf(v.x);
            As[ac4 + 1][arow] = f2tf(v.y);
            As[ac4 + 2][arow] = f2tf(v.z);
            As[ac4 + 3][arow] = f2tf(v.w);
            int brow = idx >> 5, bc4 = (idx & 31) * 4;
            float4 w = *(const float4*)&B[(size_t)(k0 + brow) * NH + bn + bc4];
            Bs[brow][bc4 + 0] = f2tf(w.x);
            Bs[brow][bc4 + 1] = f2tf(w.y);
            Bs[brow][bc4 + 2] = f2tf(w.z);
            Bs[brow][bc4 + 3] = f2tf(w.w);
        }
        __syncthreads();
#pragma unroll
        for (int ks = 0; ks < 16; ks += 8) {
            unsigned af[2][4], bf[8][2];
#pragma unroll
            for (int mi = 0; mi < 2; mi++) {
                int m0 = wm + mi * 16;
                af[mi][0] = As[ks + t][m0 + g];
                af[mi][1] = As[ks + t][m0 + g + 8];
                af[mi][2] = As[ks + t + 4][m0 + g];
                af[mi][3] = As[ks + t + 4][m0 + g + 8];
            }
#pragma unroll
            for (int ni = 0; ni < 8; ni++) {
                int n0 = wn + ni * 8;
                bf[ni][0] = Bs[ks + t][n0 + g];
                bf[ni][1] = Bs[ks + t + 4][n0 + g];
            }
#pragma unroll
            for (int mi = 0; mi < 2; mi++)
#pragma unroll
                for (int ni = 0; ni < 8; ni++)
                    mma_tf32(acc[mi][ni], af[mi], bf[ni]);
        }
        __syncthreads();
    }
#pragma unroll
    for (int mi = 0; mi < 2; mi++)
#pragma unroll
        for (int ni = 0; ni < 8; ni++) {
            int row = bm + wm + mi * 16 + g;
            int col = bn + wn + ni * 8 + 2 * t;
            *(float2*)&g_xw0[(size_t)row * NH + col] =
                make_float2(acc[mi][ni][0], acc[mi][ni][1]);
            *(float2*)&g_xw0[(size_t)(row + 8) * NH + col] =
                make_float2(acc[mi][ni][2], acc[mi][ni][3]);
        }
}

// ---------------------------------------------------------------------------
// SpMM1: g_h[r,:] = tf32(relu(sum vals*g_xw0[cols,:] + b0)).
// ---------------------------------------------------------------------------
__global__ __launch_bounds__(256) void k_spmm1(const float* __restrict__ vals,
                                               const int* __restrict__ cols,
                                               const float* __restrict__ bias) {
    int r = blockIdx.x;
    int t = threadIdx.x;
    int s = g_rowptr[r], e = g_rowptr[r + 1];
    float a0 = 0, a1 = 0, a2 = 0, a3 = 0;
    float c0 = 0, c1 = 0, c2 = 0, c3 = 0;
    int i = s;
    for (; i + 4 <= e; i += 4) {
        float v0 = vals[i], v1 = vals[i + 1], v2 = vals[i + 2], v3 = vals[i + 3];
        int   j0 = cols[i], j1 = cols[i + 1], j2 = cols[i + 2], j3 = cols[i + 3];
        a0 += v0 * g_xw0[(size_t)j0 * NH + t];
        c0 += v0 * g_xw0[(size_t)j0 * NH + t + 256];
        a1 += v1 * g_xw0[(size_t)j1 * NH + t];
        c1 += v1 * g_xw0[(size_t)j1 * NH + t + 256];
        a2 += v2 * g_xw0[(size_t)j2 * NH + t];
        c2 += v2 * g_xw0[(size_t)j2 * NH + t + 256];
        a3 += v3 * g_xw0[(size_t)j3 * NH + t];
        c3 += v3 * g_xw0[(size_t)j3 * NH + t + 256];
    }
    for (; i < e; i++) {
        float v = vals[i]; int j = cols[i];
        a0 += v * g_xw0[(size_t)j * NH + t];
        c0 += v * g_xw0[(size_t)j * NH + t + 256];
    }
    float h0 = (a0 + a1) + (a2 + a3) + bias[t];
    float h1 = (c0 + c1) + (c2 + c3) + bias[t + 256];
    g_h[(size_t)r * NH + t]       = f2tf(fmaxf(h0, 0.f));
    g_h[(size_t)r * NH + t + 256] = f2tf(fmaxf(h1, 0.f));
}

// ---------------------------------------------------------------------------
// GEMM2 (tf32 mma): g_hw = g_h[8192,512] @ g_wcat[512,64].
// 128x64 tile, BK=32, 8 warps (4M x 2N), warp tile 32x32.
// ---------------------------------------------------------------------------
__global__ __launch_bounds__(256) void k_gemm2() {
    __shared__ unsigned As[32][132];   // [k][m]
    __shared__ unsigned Bs[32][68];    // [k][n]
    int tid = threadIdx.x, lane = tid & 31, wid = tid >> 5;
    int g = lane >> 2, t = lane & 3;
    int bm = blockIdx.x * 128;
    int wm = (wid & 3) * 32, wn = (wid >> 2) * 32;

    float acc[2][4][4];
#pragma unroll
    for (int mi = 0; mi < 2; mi++)
#pragma unroll
        for (int ni = 0; ni < 4; ni++)
#pragma unroll
            for (int j = 0; j < 4; j++) acc[mi][ni][j] = 0.f;

    for (int k0 = 0; k0 < NH; k0 += 32) {
#pragma unroll
        for (int l = 0; l < 4; l++) {                 // A: 1024 uint4
            int idx = tid * 4 + l;
            int row = idx >> 3, c4 = (idx & 7) * 4;
            uint4 v = *(const uint4*)&g_h[(size_t)(bm + row) * NH + k0 + c4];
            As[c4 + 0][row] = v.x; As[c4 + 1][row] = v.y;
            As[c4 + 2][row] = v.z; As[c4 + 3][row] = v.w;
        }
#pragma unroll
        for (int l = 0; l < 2; l++) {                 // B: 512 uint4
            int idx = tid * 2 + l;
            int row = idx >> 4, c4 = (idx & 15) * 4;
            *(uint4*)&Bs[row][c4] = *(const uint4*)&g_wcat[(size_t)(k0 + row) * 64 + c4];
        }
        __syncthreads();
#pragma unroll
        for (int ks = 0; ks < 32; ks += 8) {
            unsigned af[2][4], bf[4][2];
#pragma unroll
            for (int mi = 0; mi < 2; mi++) {
                int m0 = wm + mi * 16;
                af[mi][0] = As[ks + t][m0 + g];
                af[mi][1] = As[ks + t][m0 + g + 8];
                af[mi][2] = As[ks + t + 4][m0 + g];
                af[mi][3] = As[ks + t + 4][m0 + g + 8];
            }
#pragma unroll
            for (int ni = 0; ni < 4; ni++) {
                int n0 = wn + ni * 8;
                bf[ni][0] = Bs[ks + t][n0 + g];
                bf[ni][1] = Bs[ks + t + 4][n0 + g];
            }
#pragma unroll
            for (int mi = 0; mi < 2; mi++)
#pragma unroll
                for (int ni = 0; ni < 4; ni++)
                    mma_tf32(acc[mi][ni], af[mi], bf[ni]);
        }
        __syncthreads();
    }
#pragma unroll
    for (int mi = 0; mi < 2; mi++)
#pragma unroll
        for (int ni = 0; ni < 4; ni++) {
            int row = bm + wm + mi * 16 + g;
            int col = wn + ni * 8 + 2 * t;
            *(float2*)&g_hw[(size_t)row * 64 + col] =
                make_float2(acc[mi][ni][0], acc[mi][ni][1]);
            *(float2*)&g_hw[(size_t)(row + 8) * 64 + col] =
                make_float2(acc[mi][ni][2], acc[mi][ni][3]);
        }
}

// ---------------------------------------------------------------------------
// SpMM2: mu/logvar = relu(spmm(g_hw) + bias); writes z/mu/logvar outputs
// (fp32) and g_z (tf32 bits) for the decoder.
// ---------------------------------------------------------------------------
__global__ __launch_bounds__(256) void k_spmm2(const float* __restrict__ vals,
                                               const int* __restrict__ cols,
                                               const float* __restrict__ b1,
                                               const float* __restrict__ b2,
                                               float* __restrict__ out) {
    int tx = threadIdx.x;                        // 0..63
    int r = blockIdx.x * 4 + threadIdx.y;
    int s = g_rowptr[r], e = g_rowptr[r + 1];
    float a0 = 0, a1 = 0, a2 = 0, a3 = 0;
    int i = s;
    for (; i + 4 <= e; i += 4) {
        float v0 = vals[i], v1 = vals[i + 1], v2 = vals[i + 2], v3 = vals[i + 3];
        int   j0 = cols[i], j1 = cols[i + 1], j2 = cols[i + 2], j3 = cols[i + 3];
        a0 += v0 * g_hw[(size_t)j0 * 64 + tx];
        a1 += v1 * g_hw[(size_t)j1 * 64 + tx];
        a2 += v2 * g_hw[(size_t)j2 * 64 + tx];
        a3 += v3 * g_hw[(size_t)j3 * 64 + tx];
    }
    for (; i < e; i++) {
        a0 += vals[i] * g_hw[(size_t)cols[i] * 64 + tx];
    }
    float bias = (tx < 32) ? b1[tx] : b2[tx - 32];
    float v = fmaxf((a0 + a1) + (a2 + a3) + bias, 0.f);
    g_z[(size_t)r * 64 + tx] = f2tf(v);

    size_t base = (size_t)NNODES * NNODES;       // after adj_recon
    if (tx < 32) {
        out[base + (size_t)r * NZ + tx] = v;                       // z
        out[base + (size_t)NNODES * NZ + (size_t)r * NZ + tx] = v; // mu
    } else {
        out[base + (size_t)NNODES * NZ * 2 + (size_t)r * NZ + (tx - 32)] = v; // logvar
    }
}

// ---------------------------------------------------------------------------
// Decoder (tf32 mma): adj_recon = sigmoid(z @ z^T). 128x128 tile, K=32.
// 8 warps (4M x 2N), warp tile 32x64.
// ---------------------------------------------------------------------------
__global__ __launch_bounds__(256) void k_decoder(float* __restrict__ out) {
    __shared__ unsigned zA[32][132];
    __shared__ unsigned zB[32][132];
    int tid = threadIdx.x, lane = tid & 31, wid = tid >> 5;
    int g = lane >> 2, t = lane & 3;
    int i0 = blockIdx.y * 128, j0 = blockIdx.x * 128;
    int wm = (wid & 3) * 32, wn = (wid >> 2) * 64;

#pragma unroll
    for (int l = 0; l < 4; l++) {                    // 1024 uint4 each tile
        int idx = tid * 4 + l;
        int row = idx >> 3, c4 = (idx & 7) * 4;      // c4 in 0..28
        uint4 va = *(const uint4*)&g_z[(size_t)(i0 + row) * 64 + c4];
        zA[c4 + 0][row] = va.x; zA[c4 + 1][row] = va.y;
        zA[c4 + 2][row] = va.z; zA[c4 + 3][row] = va.w;
        uint4 vb = *(const uint4*)&g_z[(size_t)(j0 + row) * 64 + c4];
        zB[c4 + 0][row] = vb.x; zB[c4 + 1][row] = vb.y;
        zB[c4 + 2][row] = vb.z; zB[c4 + 3][row] = vb.w;
    }
    __syncthreads();

    float acc[2][8][4];
#pragma unroll
    for (int mi = 0; mi < 2; mi++)
#pragma unroll
        for (int ni = 0; ni < 8; ni++)
#pragma unroll
            for (int j = 0; j < 4; j++) acc[mi][ni][j] = 0.f;

#pragma unroll
    for (int ks = 0; ks < NZ; ks += 8) {
        unsigned af[2][4], bf[8][2];
#pragma unroll
        for (int mi = 0; mi < 2; mi++) {
            int m0 = wm + mi * 16;
            af[mi][0] = zA[ks + t][m0 + g];
            af[mi][1] = zA[ks + t][m0 + g + 8];
            af[mi][2] = zA[ks + t + 4][m0 + g];
            af[mi][3] = zA[ks + t + 4][m0 + g + 8];
        }
#pragma unroll
        for (int ni = 0; ni < 8; ni++) {
            int n0 = wn + ni * 8;
            bf[ni][0] = zB[ks + t][n0 + g];
            bf[ni][1] = zB[ks + t + 4][n0 + g];
        }
#pragma unroll
        for (int mi = 0; mi < 2; mi++)
#pragma unroll
            for (int ni = 0; ni < 8; ni++)
                mma_tf32(acc[mi][ni], af[mi], bf[ni]);
    }

#pragma unroll
    for (int mi = 0; mi < 2; mi++)
#pragma unroll
        for (int ni = 0; ni < 8; ni++) {
            int row = i0 + wm + mi * 16 + g;
            int col = j0 + wn + ni * 8 + 2 * t;
            float s0 = 1.f / (1.f + __expf(-acc[mi][ni][0]));
            float s1 = 1.f / (1.f + __expf(-acc[mi][ni][1]));
            float s2 = 1.f / (1.f + __expf(-acc[mi][ni][2]));
            float s3 = 1.f / (1.f + __expf(-acc[mi][ni][3]));
            *(float2*)&out[(size_t)row * NNODES + col]       = make_float2(s0, s1);
            *(float2*)&out[(size_t)(row + 8) * NNODES + col] = make_float2(s2, s3);
        }
}

// ---------------------------------------------------------------------------
extern "C" void kernel_launch(void* const* d_in, const int* in_sizes, int n_in,
                              void* d_out, int out_size) {
    const float* x    = (const float*)d_in[0];
    const float* vals = (const float*)d_in[1];
    const float* W0   = (const float*)d_in[2];
    const float* b0   = (const float*)d_in[3];
    const float* W1   = (const float*)d_in[4];
    const float* b1   = (const float*)d_in[5];
    const float* W2   = (const float*)d_in[6];
    const float* b2   = (const float*)d_in[7];
    const int*   rows = (const int*)d_in[8];
    const int*   cols = (const int*)d_in[9];
    int E = in_sizes[1];
    float* out = (float*)d_out;

    k_rowptr<<<(NNODES + 256) / 256, 256>>>(rows, E);
    k_pack_w<<<(NH * 64 + 255) / 256, 256>>>(W1, W2);
    k_gemm1<<<dim3(NH / 128, NNODES / 128), 256>>>(x, W0);
    k_spmm1<<<NNODES, 256>>>(vals, cols, b0);
    k_gemm2<<<NNODES / 128, 256>>>();
    k_spmm2<<<NNODES / 4, dim3(64, 4)>>>(vals, cols, b1, b2, out);
    k_decoder<<<dim3(NNODES / 128, NNODES / 128), 256>>>(out);
}

// round 4
// speedup vs baseline: 1.9941x; 1.1974x over previous
#include <cuda_runtime.h>
#include <cuda_bf16.h>

#define NNODES 8192
#define NF 1024
#define NH 512
#define NZ 32

// ---- scratch (device globals; no allocation allowed) ----
__device__ __nv_bfloat162 g_xw0h[NNODES * NH / 2]; // x @ W0 (bf16 pairs)
__device__ float g_h[NNODES * NH];                 // relu(spmm + b0) fp32
__device__ float g_hw[NNODES * 64];                // h @ [W1|W2] fp32
__device__ float g_z[NNODES * 64];                 // [mu | logvar] fp32
__device__ int   g_rowptr[NNODES + 1];

__device__ __forceinline__ unsigned fu(float f) { return __float_as_uint(f); }

__device__ __forceinline__ void mma_tf32(float c[4], const unsigned a[4],
                                         const unsigned b[2]) {
    asm volatile(
        "mma.sync.aligned.m16n8k8.row.col.f32.tf32.tf32.f32 "
        "{%0,%1,%2,%3}, {%4,%5,%6,%7}, {%8,%9}, {%0,%1,%2,%3};"
        : "+f"(c[0]), "+f"(c[1]), "+f"(c[2]), "+f"(c[3])
        : "r"(a[0]), "r"(a[1]), "r"(a[2]), "r"(a[3]), "r"(b[0]), "r"(b[1]));
}

__device__ __forceinline__ void cpa16(void* s, const void* g) {
    unsigned sa = (unsigned)__cvta_generic_to_shared(s);
    asm volatile("cp.async.cg.shared.global [%0], [%1], 16;" :: "r"(sa), "l"(g));
}
__device__ __forceinline__ void cpa_commit() {
    asm volatile("cp.async.commit_group;");
}

// ---------------------------------------------------------------------------
// CSR row pointers (binary search on sorted rows).
// ---------------------------------------------------------------------------
__global__ void k_rowptr(const int* __restrict__ rows, int E) {
    int r = blockIdx.x * blockDim.x + threadIdx.x;
    if (r > NNODES) return;
    int lo = 0, hi = E;
    while (lo < hi) {
        int mid = (lo + hi) >> 1;
        if (rows[mid] < r) lo = mid + 1; else hi = mid;
    }
    g_rowptr[r] = lo;
}

// ---------------------------------------------------------------------------
// GEMM1 (tf32 mma, cp.async double-buffered): x[8192,1024] @ W0[1024,512]
// 128x128 tile, BK=16, 8 warps (4M x 2N), warp tile 32x64. Output bf16.
// As: [m][k] stride 20 (banks g*20+t mod 32 all distinct).
// Bs: [k][n] stride 136 (banks t*8+g all distinct).
// ---------------------------------------------------------------------------
__global__ __launch_bounds__(256) void k_gemm1(const float* __restrict__ A,
                                               const float* __restrict__ B) {
    __shared__ float As[2][128][20];
    __shared__ float Bs[2][16][136];
    int tid = threadIdx.x, lane = tid & 31, wid = tid >> 5;
    int g = lane >> 2, t = lane & 3;
    int bm = blockIdx.y * 128, bn = blockIdx.x * 128;
    int wm = (wid & 3) * 32, wn = (wid >> 2) * 64;

    float acc[2][8][4];
#pragma unroll
    for (int mi = 0; mi < 2; mi++)
#pragma unroll
        for (int ni = 0; ni < 8; ni++)
#pragma unroll
            for (int j = 0; j < 4; j++) acc[mi][ni][j] = 0.f;

    // precomputed load indices
    int a_row[2], a_c4[2], b_row[2], b_c4[2];
#pragma unroll
    for (int l = 0; l < 2; l++) {
        int idx = tid * 2 + l;
        a_row[l] = idx >> 2;  a_c4[l] = (idx & 3) * 4;
        b_row[l] = idx >> 5;  b_c4[l] = (idx & 31) * 4;
    }

    // issue stage 0
#pragma unroll
    for (int l = 0; l < 2; l++) {
        cpa16(&As[0][a_row[l]][a_c4[l]], &A[(size_t)(bm + a_row[l]) * NF + a_c4[l]]);
        cpa16(&Bs[0][b_row[l]][b_c4[l]], &B[(size_t)b_row[l] * NH + bn + b_c4[l]]);
    }
    cpa_commit();

    const int NKT = NF / 16;   // 64
    for (int kt = 0; kt < NKT; kt++) {
        int st = kt & 1;
        if (kt < NKT - 1) {
            int k0 = (kt + 1) * 16, ns = st ^ 1;
#pragma unroll
            for (int l = 0; l < 2; l++) {
                cpa16(&As[ns][a_row[l]][a_c4[l]],
                      &A[(size_t)(bm + a_row[l]) * NF + k0 + a_c4[l]]);
                cpa16(&Bs[ns][b_row[l]][b_c4[l]],
                      &B[(size_t)(k0 + b_row[l]) * NH + bn + b_c4[l]]);
            }
            cpa_commit();
            asm volatile("cp.async.wait_group 1;");
        } else {
            asm volatile("cp.async.wait_group 0;");
        }
        __syncthreads();
#pragma unroll
        for (int ks = 0; ks < 16; ks += 8) {
            unsigned af[2][4], bf[8][2];
#pragma unroll
            for (int mi = 0; mi < 2; mi++) {
                int m0 = wm + mi * 16;
                af[mi][0] = fu(As[st][m0 + g][ks + t]);
                af[mi][1] = fu(As[st][m0 + g + 8][ks + t]);
                af[mi][2] = fu(As[st][m0 + g][ks + t + 4]);
                af[mi][3] = fu(As[st][m0 + g + 8][ks + t + 4]);
            }
#pragma unroll
            for (int ni = 0; ni < 8; ni++) {
                int n0 = wn + ni * 8;
                bf[ni][0] = fu(Bs[st][ks + t][n0 + g]);
                bf[ni][1] = fu(Bs[st][ks + t + 4][n0 + g]);
            }
#pragma unroll
            for (int mi = 0; mi < 2; mi++)
#pragma unroll
                for (int ni = 0; ni < 8; ni++)
                    mma_tf32(acc[mi][ni], af[mi], bf[ni]);
        }
        __syncthreads();
    }
#pragma unroll
    for (int mi = 0; mi < 2; mi++)
#pragma unroll
        for (int ni = 0; ni < 8; ni++) {
            int row = bm + wm + mi * 16 + g;
            int col = bn + wn + ni * 8 + 2 * t;
            g_xw0h[((size_t)row * NH + col) >> 1] =
                __float22bfloat162_rn(make_float2(acc[mi][ni][0], acc[mi][ni][1]));
            g_xw0h[((size_t)(row + 8) * NH + col) >> 1] =
                __float22bfloat162_rn(make_float2(acc[mi][ni][2], acc[mi][ni][3]));
        }
}

// ---------------------------------------------------------------------------
// SpMM1: g_h[r,:] = relu(sum vals*xw0[cols,:] + b0). bf16x2 gather, fp32 acc.
// Thread t owns features {2t, 2t+1}.
// ---------------------------------------------------------------------------
__global__ __launch_bounds__(256) void k_spmm1(const float* __restrict__ vals,
                                               const int* __restrict__ cols,
                                               const float* __restrict__ bias) {
    int r = blockIdx.x;
    int t = threadIdx.x;
    int s = g_rowptr[r], e = g_rowptr[r + 1];
    float2 a0 = {0, 0}, a1 = {0, 0}, a2 = {0, 0}, a3 = {0, 0};
    int i = s;
    for (; i + 4 <= e; i += 4) {
        float v0 = vals[i], v1 = vals[i + 1], v2 = vals[i + 2], v3 = vals[i + 3];
        int   j0 = cols[i], j1 = cols[i + 1], j2 = cols[i + 2], j3 = cols[i + 3];
        float2 f0 = __bfloat1622float2(g_xw0h[(size_t)j0 * 256 + t]);
        float2 f1 = __bfloat1622float2(g_xw0h[(size_t)j1 * 256 + t]);
        float2 f2 = __bfloat1622float2(g_xw0h[(size_t)j2 * 256 + t]);
        float2 f3 = __bfloat1622float2(g_xw0h[(size_t)j3 * 256 + t]);
        a0.x += v0 * f0.x; a0.y += v0 * f0.y;
        a1.x += v1 * f1.x; a1.y += v1 * f1.y;
        a2.x += v2 * f2.x; a2.y += v2 * f2.y;
        a3.x += v3 * f3.x; a3.y += v3 * f3.y;
    }
    for (; i < e; i++) {
        float v = vals[i];
        float2 f = __bfloat1622float2(g_xw0h[(size_t)cols[i] * 256 + t]);
        a0.x += v * f.x; a0.y += v * f.y;
    }
    float h0 = (a0.x + a1.x) + (a2.x + a3.x) + bias[2 * t];
    float h1 = (a0.y + a1.y) + (a2.y + a3.y) + bias[2 * t + 1];
    *(float2*)&g_h[(size_t)r * NH + 2 * t] =
        make_float2(fmaxf(h0, 0.f), fmaxf(h1, 0.f));
}

// ---------------------------------------------------------------------------
// GEMM2 (tf32 mma): g_hw = g_h[8192,512] @ [W1|W2][512,64].
// 128x64 tile, BK=32, 8 warps (4M x 2N), warp tile 32x32.
// As [k][m] stride 136, Bs [k][n] stride 72 (both conflict-free).
// ---------------------------------------------------------------------------
__global__ __launch_bounds__(256) void k_gemm2(const float* __restrict__ W1,
                                               const float* __restrict__ W2) {
    __shared__ unsigned As[32][136];
    __shared__ unsigned Bs[32][72];
    int tid = threadIdx.x, lane = tid & 31, wid = tid >> 5;
    int g = lane >> 2, t = lane & 3;
    int bm = blockIdx.x * 128;
    int wm = (wid & 3) * 32, wn = (wid >> 2) * 32;

    float acc[2][4][4];
#pragma unroll
    for (int mi = 0; mi < 2; mi++)
#pragma unroll
        for (int ni = 0; ni < 4; ni++)
#pragma unroll
            for (int j = 0; j < 4; j++) acc[mi][ni][j] = 0.f;

    for (int k0 = 0; k0 < NH; k0 += 32) {
#pragma unroll
        for (int l = 0; l < 4; l++) {                 // A: 1024 float4
            int idx = tid * 4 + l;
            int row = idx >> 3, c4 = (idx & 7) * 4;
            float4 v = *(const float4*)&g_h[(size_t)(bm + row) * NH + k0 + c4];
            As[c4 + 0][row] = fu(v.x); As[c4 + 1][row] = fu(v.y);
            As[c4 + 2][row] = fu(v.z); As[c4 + 3][row] = fu(v.w);
        }
#pragma unroll
        for (int l = 0; l < 2; l++) {                 // B: 512 float4
            int idx = tid * 2 + l;
            int row = idx >> 4, c4 = (idx & 15) * 4;  // c4 in 0..60
            float4 w = (c4 < 32)
                ? *(const float4*)&W1[(size_t)(k0 + row) * NZ + c4]
                : *(const float4*)&W2[(size_t)(k0 + row) * NZ + (c4 - 32)];
            Bs[row][c4 + 0] = fu(w.x); Bs[row][c4 + 1] = fu(w.y);
            Bs[row][c4 + 2] = fu(w.z); Bs[row][c4 + 3] = fu(w.w);
        }
        __syncthreads();
#pragma unroll
        for (int ks = 0; ks < 32; ks += 8) {
            unsigned af[2][4], bf[4][2];
#pragma unroll
            for (int mi = 0; mi < 2; mi++) {
                int m0 = wm + mi * 16;
                af[mi][0] = As[ks + t][m0 + g];
                af[mi][1] = As[ks + t][m0 + g + 8];
                af[mi][2] = As[ks + t + 4][m0 + g];
                af[mi][3] = As[ks + t + 4][m0 + g + 8];
            }
#pragma unroll
            for (int ni = 0; ni < 4; ni++) {
                int n0 = wn + ni * 8;
                bf[ni][0] = Bs[ks + t][n0 + g];
                bf[ni][1] = Bs[ks + t + 4][n0 + g];
            }
#pragma unroll
            for (int mi = 0; mi < 2; mi++)
#pragma unroll
                for (int ni = 0; ni < 4; ni++)
                    mma_tf32(acc[mi][ni], af[mi], bf[ni]);
        }
        __syncthreads();
    }
#pragma unroll
    for (int mi = 0; mi < 2; mi++)
#pragma unroll
        for (int ni = 0; ni < 4; ni++) {
            int row = bm + wm + mi * 16 + g;
            int col = wn + ni * 8 + 2 * t;
            *(float2*)&g_hw[(size_t)row * 64 + col] =
                make_float2(acc[mi][ni][0], acc[mi][ni][1]);
            *(float2*)&g_hw[(size_t)(row + 8) * 64 + col] =
                make_float2(acc[mi][ni][2], acc[mi][ni][3]);
        }
}

// ---------------------------------------------------------------------------
// SpMM2: mu/logvar = relu(spmm(g_hw) + bias); writes z/mu/logvar to out and
// g_z (fp32) for the decoder.
// ---------------------------------------------------------------------------
__global__ __launch_bounds__(256) void k_spmm2(const float* __restrict__ vals,
                                               const int* __restrict__ cols,
                                               const float* __restrict__ b1,
                                               const float* __restrict__ b2,
                                               float* __restrict__ out) {
    int tx = threadIdx.x;                        // 0..63
    int r = blockIdx.x * 4 + threadIdx.y;
    int s = g_rowptr[r], e = g_rowptr[r + 1];
    float a0 = 0, a1 = 0, a2 = 0, a3 = 0;
    int i = s;
    for (; i + 4 <= e; i += 4) {
        float v0 = vals[i], v1 = vals[i + 1], v2 = vals[i + 2], v3 = vals[i + 3];
        int   j0 = cols[i], j1 = cols[i + 1], j2 = cols[i + 2], j3 = cols[i + 3];
        a0 += v0 * g_hw[(size_t)j0 * 64 + tx];
        a1 += v1 * g_hw[(size_t)j1 * 64 + tx];
        a2 += v2 * g_hw[(size_t)j2 * 64 + tx];
        a3 += v3 * g_hw[(size_t)j3 * 64 + tx];
    }
    for (; i < e; i++) {
        a0 += vals[i] * g_hw[(size_t)cols[i] * 64 + tx];
    }
    float bias = (tx < 32) ? b1[tx] : b2[tx - 32];
    float v = fmaxf((a0 + a1) + (a2 + a3) + bias, 0.f);
    g_z[(size_t)r * 64 + tx] = v;

    size_t base = (size_t)NNODES * NNODES;       // after adj_recon
    if (tx < 32) {
        out[base + (size_t)r * NZ + tx] = v;                       // z
        out[base + (size_t)NNODES * NZ + (size_t)r * NZ + tx] = v; // mu
    } else {
        out[base + (size_t)NNODES * NZ * 2 + (size_t)r * NZ + (tx - 32)] = v; // logvar
    }
}

// ---------------------------------------------------------------------------
// Decoder (tf32 mma): adj_recon = sigmoid(z @ z^T). 128x128 tile, K=32.
// 8 warps (4M x 2N), warp tile 32x64. smem stride 136 (conflict-free).
// ---------------------------------------------------------------------------
__global__ __launch_bounds__(256) void k_decoder(float* __restrict__ out) {
    __shared__ unsigned zA[32][136];
    __shared__ unsigned zB[32][136];
    int tid = threadIdx.x, lane = tid & 31, wid = tid >> 5;
    int g = lane >> 2, t = lane & 3;
    int i0 = blockIdx.y * 128, j0 = blockIdx.x * 128;
    int wm = (wid & 3) * 32, wn = (wid >> 2) * 64;

#pragma unroll
    for (int l = 0; l < 4; l++) {                    // 1024 float4 each tile
        int idx = tid * 4 + l;
        int row = idx >> 3, c4 = (idx & 7) * 4;      // cols 0..31 (= z)
        float4 va = *(const float4*)&g_z[(size_t)(i0 + row) * 64 + c4];
        zA[c4 + 0][row] = fu(va.x); zA[c4 + 1][row] = fu(va.y);
        zA[c4 + 2][row] = fu(va.z); zA[c4 + 3][row] = fu(va.w);
        float4 vb = *(const float4*)&g_z[(size_t)(j0 + row) * 64 + c4];
        zB[c4 + 0][row] = fu(vb.x); zB[c4 + 1][row] = fu(vb.y);
        zB[c4 + 2][row] = fu(vb.z); zB[c4 + 3][row] = fu(vb.w);
    }
    __syncthreads();

    float acc[2][8][4];
#pragma unroll
    for (int mi = 0; mi < 2; mi++)
#pragma unroll
        for (int ni = 0; ni < 8; ni++)
#pragma unroll
            for (int j = 0; j < 4; j++) acc[mi][ni][j] = 0.f;

#pragma unroll
    for (int ks = 0; ks < NZ; ks += 8) {
        unsigned af[2][4], bf[8][2];
#pragma unroll
        for (int mi = 0; mi < 2; mi++) {
            int m0 = wm + mi * 16;
            af[mi][0] = zA[ks + t][m0 + g];
            af[mi][1] = zA[ks + t][m0 + g + 8];
            af[mi][2] = zA[ks + t + 4][m0 + g];
            af[mi][3] = zA[ks + t + 4][m0 + g + 8];
        }
#pragma unroll
        for (int ni = 0; ni < 8; ni++) {
            int n0 = wn + ni * 8;
            bf[ni][0] = zB[ks + t][n0 + g];
            bf[ni][1] = zB[ks + t + 4][n0 + g];
        }
#pragma unroll
        for (int mi = 0; mi < 2; mi++)
#pragma unroll
            for (int ni = 0; ni < 8; ni++)
                mma_tf32(acc[mi][ni], af[mi], bf[ni]);
    }

#pragma unroll
    for (int mi = 0; mi < 2; mi++)
#pragma unroll
        for (int ni = 0; ni < 8; ni++) {
            int row = i0 + wm + mi * 16 + g;
            int col = j0 + wn + ni * 8 + 2 * t;
            float s0 = 1.f / (1.f + __expf(-acc[mi][ni][0]));
            float s1 = 1.f / (1.f + __expf(-acc[mi][ni][1]));
            float s2 = 1.f / (1.f + __expf(-acc[mi][ni][2]));
            float s3 = 1.f / (1.f + __expf(-acc[mi][ni][3]));
            *(float2*)&out[(size_t)row * NNODES + col]       = make_float2(s0, s1);
            *(float2*)&out[(size_t)(row + 8) * NNODES + col] = make_float2(s2, s3);
        }
}

// ---------------------------------------------------------------------------
extern "C" void kernel_launch(void* const* d_in, const int* in_sizes, int n_in,
                              void* d_out, int out_size) {
    const float* x    = (const float*)d_in[0];
    const float* vals = (const float*)d_in[1];
    const float* W0   = (const float*)d_in[2];
    const float* b0   = (const float*)d_in[3];
    const float* W1   = (const float*)d_in[4];
    const float* b1   = (const float*)d_in[5];
    const float* W2   = (const float*)d_in[6];
    const float* b2   = (const float*)d_in[7];
    const int*   rows = (const int*)d_in[8];
    const int*   cols = (const int*)d_in[9];
    int E = in_sizes[1];
    float* out = (float*)d_out;

    k_rowptr<<<(NNODES + 256) / 256, 256>>>(rows, E);
    k_gemm1<<<dim3(NH / 128, NNODES / 128), 256>>>(x, W0);
    k_spmm1<<<NNODES, 256>>>(vals, cols, b0);
    k_gemm2<<<NNODES / 128, 256>>>(W1, W2);
    k_spmm2<<<NNODES / 4, dim3(64, 4)>>>(vals, cols, b1, b2, out);
    k_decoder<<<dim3(NNODES / 128, NNODES / 128), 256>>>(out);
}

// round 5
// speedup vs baseline: 2.1837x; 1.0951x over previous
#include <cuda_runtime.h>
#include <cuda_bf16.h>

#define NNODES 8192
#define NF 1024
#define NH 512
#define NZ 32

// ---- scratch (device globals; no allocation allowed) ----
__device__ unsigned g_xr[NNODES * NF];             // x rounded to tf32 (RNA)
__device__ unsigned g_w0r[NF * NH];                // W0 rounded to tf32 (RNA)
__device__ __nv_bfloat162 g_xw0h[NNODES * NH / 2]; // x @ W0 (bf16 pairs)
__device__ float g_h[NNODES * NH];                 // relu(spmm + b0) fp32
__device__ float g_hw[NNODES * 64];                // h @ [W1|W2] fp32
__device__ float g_z[NNODES * 64];                 // [mu | logvar] fp32
__device__ int   g_rowptr[NNODES + 1];

__device__ __forceinline__ unsigned f2tf(float f) {
    unsigned u;
    asm("cvt.rna.tf32.f32 %0, %1;" : "=r"(u) : "f"(f));
    return u;
}

__device__ __forceinline__ void mma_tf32(float c[4], const unsigned a[4],
                                         const unsigned b[2]) {
    asm volatile(
        "mma.sync.aligned.m16n8k8.row.col.f32.tf32.tf32.f32 "
        "{%0,%1,%2,%3}, {%4,%5,%6,%7}, {%8,%9}, {%0,%1,%2,%3};"
        : "+f"(c[0]), "+f"(c[1]), "+f"(c[2]), "+f"(c[3])
        : "r"(a[0]), "r"(a[1]), "r"(a[2]), "r"(a[3]), "r"(b[0]), "r"(b[1]));
}

__device__ __forceinline__ void cpa16(void* s, const void* g) {
    unsigned sa = (unsigned)__cvta_generic_to_shared(s);
    asm volatile("cp.async.cg.shared.global [%0], [%1], 16;" :: "r"(sa), "l"(g));
}
__device__ __forceinline__ void cpa_commit() {
    asm volatile("cp.async.commit_group;");
}

__device__ __forceinline__ float fast_sigmoid(float x) {
    float th;
    asm("tanh.approx.f32 %0, %1;" : "=f"(th) : "f"(0.5f * x));
    return fmaf(0.5f, th, 0.5f);
}

// ---------------------------------------------------------------------------
// CSR row pointers (binary search on sorted rows).
// ---------------------------------------------------------------------------
__global__ void k_rowptr(const int* __restrict__ rows, int E) {
    int r = blockIdx.x * blockDim.x + threadIdx.x;
    if (r > NNODES) return;
    int lo = 0, hi = E;
    while (lo < hi) {
        int mid = (lo + hi) >> 1;
        if (rows[mid] < r) lo = mid + 1; else hi = mid;
    }
    g_rowptr[r] = lo;
}

// ---------------------------------------------------------------------------
// Round fp32 -> tf32 bits (RNA). n must be a multiple of 4.
// ---------------------------------------------------------------------------
__global__ void k_round(const float* __restrict__ src, unsigned* __restrict__ dst,
                        int n4) {
    int i = blockIdx.x * blockDim.x + threadIdx.x;
    if (i >= n4) return;
    float4 v = ((const float4*)src)[i];
    uint4 o;
    o.x = f2tf(v.x); o.y = f2tf(v.y); o.z = f2tf(v.z); o.w = f2tf(v.w);
    ((uint4*)dst)[i] = o;
}

// ---------------------------------------------------------------------------
// GEMM1 (tf32 mma, cp.async double-buffered): xr[8192,1024] @ w0r[1024,512]
// 128x128 tile, BK=16, 8 warps (4M x 2N), warp tile 32x64. Output bf16.
// Inputs are pre-rounded tf32 bits (RNA, unbiased).
// ---------------------------------------------------------------------------
__global__ __launch_bounds__(256) void k_gemm1() {
    __shared__ unsigned As[2][128][20];
    __shared__ unsigned Bs[2][16][136];
    int tid = threadIdx.x, lane = tid & 31, wid = tid >> 5;
    int g = lane >> 2, t = lane & 3;
    int bm = blockIdx.y * 128, bn = blockIdx.x * 128;
    int wm = (wid & 3) * 32, wn = (wid >> 2) * 64;

    float acc[2][8][4];
#pragma unroll
    for (int mi = 0; mi < 2; mi++)
#pragma unroll
        for (int ni = 0; ni < 8; ni++)
#pragma unroll
            for (int j = 0; j < 4; j++) acc[mi][ni][j] = 0.f;

    int a_row[2], a_c4[2], b_row[2], b_c4[2];
#pragma unroll
    for (int l = 0; l < 2; l++) {
        int idx = tid * 2 + l;
        a_row[l] = idx >> 2;  a_c4[l] = (idx & 3) * 4;
        b_row[l] = idx >> 5;  b_c4[l] = (idx & 31) * 4;
    }

#pragma unroll
    for (int l = 0; l < 2; l++) {
        cpa16(&As[0][a_row[l]][a_c4[l]], &g_xr[(size_t)(bm + a_row[l]) * NF + a_c4[l]]);
        cpa16(&Bs[0][b_row[l]][b_c4[l]], &g_w0r[(size_t)b_row[l] * NH + bn + b_c4[l]]);
    }
    cpa_commit();

    const int NKT = NF / 16;   // 64
    for (int kt = 0; kt < NKT; kt++) {
        int st = kt & 1;
        if (kt < NKT - 1) {
            int k0 = (kt + 1) * 16, ns = st ^ 1;
#pragma unroll
            for (int l = 0; l < 2; l++) {
                cpa16(&As[ns][a_row[l]][a_c4[l]],
                      &g_xr[(size_t)(bm + a_row[l]) * NF + k0 + a_c4[l]]);
                cpa16(&Bs[ns][b_row[l]][b_c4[l]],
                      &g_w0r[(size_t)(k0 + b_row[l]) * NH + bn + b_c4[l]]);
            }
            cpa_commit();
            asm volatile("cp.async.wait_group 1;");
        } else {
            asm volatile("cp.async.wait_group 0;");
        }
        __syncthreads();
#pragma unroll
        for (int ks = 0; ks < 16; ks += 8) {
            unsigned af[2][4], bf[8][2];
#pragma unroll
            for (int mi = 0; mi < 2; mi++) {
                int m0 = wm + mi * 16;
                af[mi][0] = As[st][m0 + g][ks + t];
                af[mi][1] = As[st][m0 + g + 8][ks + t];
                af[mi][2] = As[st][m0 + g][ks + t + 4];
                af[mi][3] = As[st][m0 + g + 8][ks + t + 4];
            }
#pragma unroll
            for (int ni = 0; ni < 8; ni++) {
                int n0 = wn + ni * 8;
                bf[ni][0] = Bs[st][ks + t][n0 + g];
                bf[ni][1] = Bs[st][ks + t + 4][n0 + g];
            }
#pragma unroll
            for (int mi = 0; mi < 2; mi++)
#pragma unroll
                for (int ni = 0; ni < 8; ni++)
                    mma_tf32(acc[mi][ni], af[mi], bf[ni]);
        }
        __syncthreads();
    }
#pragma unroll
    for (int mi = 0; mi < 2; mi++)
#pragma unroll
        for (int ni = 0; ni < 8; ni++) {
            int row = bm + wm + mi * 16 + g;
            int col = bn + wn + ni * 8 + 2 * t;
            g_xw0h[((size_t)row * NH + col) >> 1] =
                __float22bfloat162_rn(make_float2(acc[mi][ni][0], acc[mi][ni][1]));
            g_xw0h[((size_t)(row + 8) * NH + col) >> 1] =
                __float22bfloat162_rn(make_float2(acc[mi][ni][2], acc[mi][ni][3]));
        }
}

// ---------------------------------------------------------------------------
// SpMM1: g_h[r,:] = relu(sum vals*xw0[cols,:] + b0). bf16x2 gather, fp32 acc.
// ---------------------------------------------------------------------------
__global__ __launch_bounds__(256) void k_spmm1(const float* __restrict__ vals,
                                               const int* __restrict__ cols,
                                               const float* __restrict__ bias) {
    int r = blockIdx.x;
    int t = threadIdx.x;
    int s = g_rowptr[r], e = g_rowptr[r + 1];
    float2 a0 = {0, 0}, a1 = {0, 0}, a2 = {0, 0}, a3 = {0, 0};
    int i = s;
    for (; i + 4 <= e; i += 4) {
        float v0 = vals[i], v1 = vals[i + 1], v2 = vals[i + 2], v3 = vals[i + 3];
        int   j0 = cols[i], j1 = cols[i + 1], j2 = cols[i + 2], j3 = cols[i + 3];
        float2 f0 = __bfloat1622float2(g_xw0h[(size_t)j0 * 256 + t]);
        float2 f1 = __bfloat1622float2(g_xw0h[(size_t)j1 * 256 + t]);
        float2 f2 = __bfloat1622float2(g_xw0h[(size_t)j2 * 256 + t]);
        float2 f3 = __bfloat1622float2(g_xw0h[(size_t)j3 * 256 + t]);
        a0.x += v0 * f0.x; a0.y += v0 * f0.y;
        a1.x += v1 * f1.x; a1.y += v1 * f1.y;
        a2.x += v2 * f2.x; a2.y += v2 * f2.y;
        a3.x += v3 * f3.x; a3.y += v3 * f3.y;
    }
    for (; i < e; i++) {
        float v = vals[i];
        float2 f = __bfloat1622float2(g_xw0h[(size_t)cols[i] * 256 + t]);
        a0.x += v * f.x; a0.y += v * f.y;
    }
    float h0 = (a0.x + a1.x) + (a2.x + a3.x) + bias[2 * t];
    float h1 = (a0.y + a1.y) + (a2.y + a3.y) + bias[2 * t + 1];
    *(float2*)&g_h[(size_t)r * NH + 2 * t] =
        make_float2(fmaxf(h0, 0.f), fmaxf(h1, 0.f));
}

// ---------------------------------------------------------------------------
// GEMM2 (tf32 mma): g_hw = g_h[8192,512] @ [W1|W2][512,64].
// BM=32 -> grid 256 (fixes grid starvation). BK=32, 8 warps (2M x 4N),
// warp tile 16x16. RNA conversion at smem fill.
// ---------------------------------------------------------------------------
__global__ __launch_bounds__(256) void k_gemm2(const float* __restrict__ W1,
                                               const float* __restrict__ W2) {
    __shared__ unsigned As[32][40];   // [k][m], stride 40 = 8 mod 32
    __shared__ unsigned Bs[32][72];   // [k][n], stride 72 = 8 mod 32
    int tid = threadIdx.x, lane = tid & 31, wid = tid >> 5;
    int g = lane >> 2, t = lane & 3;
    int bm = blockIdx.x * 32;
    int wm = (wid & 1) * 16, wn = (wid >> 1) * 16;

    float acc[2][4];
#pragma unroll
    for (int ni = 0; ni < 2; ni++)
#pragma unroll
        for (int j = 0; j < 4; j++) acc[ni][j] = 0.f;

    for (int k0 = 0; k0 < NH; k0 += 32) {
        {   // A: 32 rows x 32 k = 256 float4, 1 per thread
            int row = tid >> 3, c4 = (tid & 7) * 4;
            float4 v = *(const float4*)&g_h[(size_t)(bm + row) * NH + k0 + c4];
            As[c4 + 0][row] = f2tf(v.x); As[c4 + 1][row] = f2tf(v.y);
            As[c4 + 2][row] = f2tf(v.z); As[c4 + 3][row] = f2tf(v.w);
        }
#pragma unroll
        for (int l = 0; l < 2; l++) {   // B: 32 rows x 64 cols = 512 float4
            int idx = tid * 2 + l;
            int row = idx >> 4, c4 = (idx & 15) * 4;
            float4 w = (c4 < 32)
                ? *(const float4*)&W1[(size_t)(k0 + row) * NZ + c4]
                : *(const float4*)&W2[(size_t)(k0 + row) * NZ + (c4 - 32)];
            Bs[row][c4 + 0] = f2tf(w.x); Bs[row][c4 + 1] = f2tf(w.y);
            Bs[row][c4 + 2] = f2tf(w.z); Bs[row][c4 + 3] = f2tf(w.w);
        }
        __syncthreads();
#pragma unroll
        for (int ks = 0; ks < 32; ks += 8) {
            unsigned af[4], bf[2][2];
            af[0] = As[ks + t][wm + g];
            af[1] = As[ks + t][wm + g + 8];
            af[2] = As[ks + t + 4][wm + g];
            af[3] = As[ks + t + 4][wm + g + 8];
#pragma unroll
            for (int ni = 0; ni < 2; ni++) {
                int n0 = wn + ni * 8;
                bf[ni][0] = Bs[ks + t][n0 + g];
                bf[ni][1] = Bs[ks + t + 4][n0 + g];
            }
#pragma unroll
            for (int ni = 0; ni < 2; ni++)
                mma_tf32(acc[ni], af, bf[ni]);
        }
        __syncthreads();
    }
#pragma unroll
    for (int ni = 0; ni < 2; ni++) {
        int row = bm + wm + g;
        int col = wn + ni * 8 + 2 * t;
        *(float2*)&g_hw[(size_t)row * 64 + col] = make_float2(acc[ni][0], acc[ni][1]);
        *(float2*)&g_hw[(size_t)(row + 8) * 64 + col] = make_float2(acc[ni][2], acc[ni][3]);
    }
}

// ---------------------------------------------------------------------------
// SpMM2: mu/logvar = relu(spmm(g_hw) + bias); writes z/mu/logvar to out and
// g_z (fp32) for the decoder.
// ---------------------------------------------------------------------------
__global__ __launch_bounds__(256) void k_spmm2(const float* __restrict__ vals,
                                               const int* __restrict__ cols,
                                               const float* __restrict__ b1,
                                               const float* __restrict__ b2,
                                               float* __restrict__ out) {
    int tx = threadIdx.x;                        // 0..63
    int r = blockIdx.x * 4 + threadIdx.y;
    int s = g_rowptr[r], e = g_rowptr[r + 1];
    float a0 = 0, a1 = 0, a2 = 0, a3 = 0;
    int i = s;
    for (; i + 4 <= e; i += 4) {
        float v0 = vals[i], v1 = vals[i + 1], v2 = vals[i + 2], v3 = vals[i + 3];
        int   j0 = cols[i], j1 = cols[i + 1], j2 = cols[i + 2], j3 = cols[i + 3];
        a0 += v0 * g_hw[(size_t)j0 * 64 + tx];
        a1 += v1 * g_hw[(size_t)j1 * 64 + tx];
        a2 += v2 * g_hw[(size_t)j2 * 64 + tx];
        a3 += v3 * g_hw[(size_t)j3 * 64 + tx];
    }
    for (; i < e; i++) {
        a0 += vals[i] * g_hw[(size_t)cols[i] * 64 + tx];
    }
    float bias = (tx < 32) ? b1[tx] : b2[tx - 32];
    float v = fmaxf((a0 + a1) + (a2 + a3) + bias, 0.f);
    g_z[(size_t)r * 64 + tx] = v;

    size_t base = (size_t)NNODES * NNODES;       // after adj_recon
    if (tx < 32) {
        out[base + (size_t)r * NZ + tx] = v;                       // z
        out[base + (size_t)NNODES * NZ + (size_t)r * NZ + tx] = v; // mu
    } else {
        out[base + (size_t)NNODES * NZ * 2 + (size_t)r * NZ + (tx - 32)] = v; // logvar
    }
}

// ---------------------------------------------------------------------------
// Decoder (tf32 mma): adj_recon = sigmoid(z @ z^T). 128x128 tile, K=32.
// 8 warps (4M x 2N), warp tile 32x64. RNA fill; sigmoid via tanh.approx.
// ---------------------------------------------------------------------------
__global__ __launch_bounds__(256) void k_decoder(float* __restrict__ out) {
    __shared__ unsigned zA[32][136];
    __shared__ unsigned zB[32][136];
    int tid = threadIdx.x, lane = tid & 31, wid = tid >> 5;
    int g = lane >> 2, t = lane & 3;
    int i0 = blockIdx.y * 128, j0 = blockIdx.x * 128;
    int wm = (wid & 3) * 32, wn = (wid >> 2) * 64;

#pragma unroll
    for (int l = 0; l < 4; l++) {                    // 1024 float4 each tile
        int idx = tid * 4 + l;
        int row = idx >> 3, c4 = (idx & 7) * 4;      // cols 0..31 (= z)
        float4 va = *(const float4*)&g_z[(size_t)(i0 + row) * 64 + c4];
        zA[c4 + 0][row] = f2tf(va.x); zA[c4 + 1][row] = f2tf(va.y);
        zA[c4 + 2][row] = f2tf(va.z); zA[c4 + 3][row] = f2tf(va.w);
        float4 vb = *(const float4*)&g_z[(size_t)(j0 + row) * 64 + c4];
        zB[c4 + 0][row] = f2tf(vb.x); zB[c4 + 1][row] = f2tf(vb.y);
        zB[c4 + 2][row] = f2tf(vb.z); zB[c4 + 3][row] = f2tf(vb.w);
    }
    __syncthreads();

    float acc[2][8][4];
#pragma unroll
    for (int mi = 0; mi < 2; mi++)
#pragma unroll
        for (int ni = 0; ni < 8; ni++)
#pragma unroll
            for (int j = 0; j < 4; j++) acc[mi][ni][j] = 0.f;

#pragma unroll
    for (int ks = 0; ks < NZ; ks += 8) {
        unsigned af[2][4], bf[8][2];
#pragma unroll
        for (int mi = 0; mi < 2; mi++) {
            int m0 = wm + mi * 16;
            af[mi][0] = zA[ks + t][m0 + g];
            af[mi][1] = zA[ks + t][m0 + g + 8];
            af[mi][2] = zA[ks + t + 4][m0 + g];
            af[mi][3] = zA[ks + t + 4][m0 + g + 8];
        }
#pragma unroll
        for (int ni = 0; ni < 8; ni++) {
            int n0 = wn + ni * 8;
            bf[ni][0] = zB[ks + t][n0 + g];
            bf[ni][1] = zB[ks + t + 4][n0 + g];
        }
#pragma unroll
        for (int mi = 0; mi < 2; mi++)
#pragma unroll
            for (int ni = 0; ni < 8; ni++)
                mma_tf32(acc[mi][ni], af[mi], bf[ni]);
    }

#pragma unroll
    for (int mi = 0; mi < 2; mi++)
#pragma unroll
        for (int ni = 0; ni < 8; ni++) {
            int row = i0 + wm + mi * 16 + g;
            int col = j0 + wn + ni * 8 + 2 * t;
            float s0 = fast_sigmoid(acc[mi][ni][0]);
            float s1 = fast_sigmoid(acc[mi][ni][1]);
            float s2 = fast_sigmoid(acc[mi][ni][2]);
            float s3 = fast_sigmoid(acc[mi][ni][3]);
            *(float2*)&out[(size_t)row * NNODES + col]       = make_float2(s0, s1);
            *(float2*)&out[(size_t)(row + 8) * NNODES + col] = make_float2(s2, s3);
        }
}

// ---------------------------------------------------------------------------
extern "C" void kernel_launch(void* const* d_in, const int* in_sizes, int n_in,
                              void* d_out, int out_size) {
    const float* x    = (const float*)d_in[0];
    const float* vals = (const float*)d_in[1];
    const float* W0   = (const float*)d_in[2];
    const float* b0   = (const float*)d_in[3];
    const float* W1   = (const float*)d_in[4];
    const float* b1   = (const float*)d_in[5];
    const float* W2   = (const float*)d_in[6];
    const float* b2   = (const float*)d_in[7];
    const int*   rows = (const int*)d_in[8];
    const int*   cols = (const int*)d_in[9];
    int E = in_sizes[1];
    float* out = (float*)d_out;

    unsigned* xr  = nullptr;  cudaGetSymbolAddress((void**)&xr,  g_xr);
    unsigned* w0r = nullptr;  cudaGetSymbolAddress((void**)&w0r, g_w0r);

    k_rowptr<<<(NNODES + 256) / 256, 256>>>(rows, E);
    k_round<<<(NNODES * NF / 4 + 255) / 256, 256>>>(x, xr, NNODES * NF / 4);
    k_round<<<(NF * NH / 4 + 255) / 256, 256>>>(W0, w0r, NF * NH / 4);
    k_gemm1<<<dim3(NH / 128, NNODES / 128), 256>>>();
    k_spmm1<<<NNODES, 256>>>(vals, cols, b0);
    k_gemm2<<<NNODES / 32, 256>>>(W1, W2);
    k_spmm2<<<NNODES / 4, dim3(64, 4)>>>(vals, cols, b1, b2, out);
    k_decoder<<<dim3(NNODES / 128, NNODES / 128), 256>>>(out);
}